// round 10
// baseline (speedup 1.0000x reference)
#include <cuda_runtime.h>
#include <cuda_bf16.h>
#include <math.h>
#include <cstdint>

#define SDIM 4096
#define CDIM 256
#define EDIM 128
#define NBATCH 4

// ---- scratch (device globals: allocation-free) ----
// tp rows = spatial s/t, 512 cols: [0:128)=theta, [128:256)=phi, [256:512)=xp^T (= (proj_w@x)[o,t])
__device__ __nv_bfloat16 g_tp[(size_t)NBATCH * SDIM * 512];
__device__ __nv_bfloat16 g_f [(size_t)NBATCH * SDIM * SDIM];       // unnormalized exp(logits)
__device__ __nv_bfloat16 g_w2[512 * 256];                          // rows: 0-127 theta_w, 128-255 phi_w, 256-511 proj_w
__device__ float         g_Z [(size_t)NBATCH * SDIM];              // row sums

// ============================ low-level helpers ============================
__device__ __forceinline__ uint32_t smem_u32(const void* p) {
    uint32_t a;
    asm("{ .reg .u64 t; cvta.to.shared.u64 t, %1; cvt.u32.u64 %0, t; }" : "=r"(a) : "l"(p));
    return a;
}
__device__ __forceinline__ void ldsm4(uint32_t r[4], uint32_t addr) {
    asm volatile("ldmatrix.sync.aligned.m8n8.x4.shared.b16 {%0,%1,%2,%3}, [%4];"
                 : "=r"(r[0]), "=r"(r[1]), "=r"(r[2]), "=r"(r[3]) : "r"(addr));
}
__device__ __forceinline__ void ldsm4t(uint32_t r[4], uint32_t addr) {
    asm volatile("ldmatrix.sync.aligned.m8n8.x4.trans.shared.b16 {%0,%1,%2,%3}, [%4];"
                 : "=r"(r[0]), "=r"(r[1]), "=r"(r[2]), "=r"(r[3]) : "r"(addr));
}
__device__ __forceinline__ void mma16816(float c[4], const uint32_t a[4], uint32_t b0, uint32_t b1) {
    asm volatile("mma.sync.aligned.m16n8k16.row.col.f32.bf16.bf16.f32 "
                 "{%0,%1,%2,%3},{%4,%5,%6,%7},{%8,%9},{%0,%1,%2,%3};"
                 : "+f"(c[0]), "+f"(c[1]), "+f"(c[2]), "+f"(c[3])
                 : "r"(a[0]), "r"(a[1]), "r"(a[2]), "r"(a[3]), "r"(b0), "r"(b1));
}
__device__ __forceinline__ void cp16(uint32_t saddr, const void* g) {
    asm volatile("cp.async.cg.shared.global [%0], [%1], 16;" :: "r"(saddr), "l"(g));
}
#define CP_COMMIT() asm volatile("cp.async.commit_group;" ::: "memory")
#define CP_WAIT(N)  asm volatile("cp.async.wait_group %0;" :: "n"(N) : "memory")

__device__ __forceinline__ uint32_t bfbits(__nv_bfloat162 h) {
    return *reinterpret_cast<uint32_t*>(&h);
}
// load 8 consecutive fp32 and convert to 4x bf16x2
__device__ __forceinline__ void ldg_cvt8(const float* g, uint32_t o[4]) {
    const float4 a = *reinterpret_cast<const float4*>(g);
    const float4 b = *reinterpret_cast<const float4*>(g + 4);
    o[0] = bfbits(__floats2bfloat162_rn(a.x, a.y));
    o[1] = bfbits(__floats2bfloat162_rn(a.z, a.w));
    o[2] = bfbits(__floats2bfloat162_rn(b.x, b.y));
    o[3] = bfbits(__floats2bfloat162_rn(b.z, b.w));
}
__device__ __forceinline__ void sts128(uint32_t addr, const uint32_t v[4]) {
    asm volatile("st.shared.v4.b32 [%0], {%1,%2,%3,%4};"
                 :: "r"(addr), "r"(v[0]), "r"(v[1]), "r"(v[2]), "r"(v[3]) : "memory");
}

// R rows x 64 cols bf16 (128B rows), XOR-16B swizzle keyed on row&7. NT threads.
template<int R, int NT>
__device__ __forceinline__ void load_tileT(uint32_t sdst, const __nv_bfloat16* g, int ldg) {
    const int tid = threadIdx.x;
    #pragma unroll
    for (int i = 0; i < (R * 8) / NT; i++) {
        const int c = tid + i * NT;
        const int r = c >> 3, kc = c & 7;
        const uint32_t so = sdst + r * 128 + (((uint32_t)kc * 16) ^ ((r & 7) * 16));
        cp16(so, g + (size_t)r * ldg + kc * 8);
    }
}
// 64 rows x 128 cols bf16 (256B rows), 256 threads (trans-A operand tile, bf16 source).
__device__ __forceinline__ void load_tile_64x128(uint32_t sdst, const __nv_bfloat16* g, int ldg) {
    const int tid = threadIdx.x;
    #pragma unroll
    for (int i = 0; i < 4; i++) {
        const int c = tid + i * 256;
        const int r = c >> 4, kc = c & 15;
        const uint32_t so = sdst + r * 256 + (((uint32_t)kc * 16) ^ ((r & 7) * 16));
        cp16(so, g + (size_t)r * ldg + kc * 8);
    }
}

// ---- 64x32 warp-tile chunk (regular A) ----
__device__ __forceinline__ void compute_chunk(uint32_t sA, uint32_t sB,
                                              int m_base, int n_base, int lane,
                                              float acc[4][4][4]) {
    #pragma unroll
    for (int ks = 0; ks < 4; ks++) {
        const int kc = ks * 2 + (lane >> 4);
        uint32_t a[4][4];
        #pragma unroll
        for (int mi = 0; mi < 4; mi++) {
            const int row = m_base + mi * 16 + (lane & 15);
            ldsm4(a[mi], sA + row * 128 + (((uint32_t)kc * 16) ^ ((row & 7) * 16)));
        }
        uint32_t b[4][2];
        #pragma unroll
        for (int nh = 0; nh < 2; nh++) {
            const int row = n_base + nh * 16 + (lane & 15);
            uint32_t r4[4];
            ldsm4(r4, sB + row * 128 + (((uint32_t)kc * 16) ^ ((row & 7) * 16)));
            b[nh * 2 + 0][0] = r4[0]; b[nh * 2 + 0][1] = r4[2];
            b[nh * 2 + 1][0] = r4[1]; b[nh * 2 + 1][1] = r4[3];
        }
        #pragma unroll
        for (int mi = 0; mi < 4; mi++)
            #pragma unroll
            for (int ni = 0; ni < 4; ni++)
                mma16816(acc[mi][ni], a[mi], b[ni][0], b[ni][1]);
    }
}

// ---- trans-A chunk: A stored [k][m] (64 rows x 128 cols, 256B rows), B regular [n][k] ----
__device__ __forceinline__ void compute_chunk_At(uint32_t sA, uint32_t sB,
                                                 int wm, int wn, int lane,
                                                 float acc[4][4][4]) {
    #pragma unroll
    for (int ks = 0; ks < 4; ks++) {
        uint32_t a[4][4];
        const int crow_l = ks * 16 + (lane & 7) + ((lane >> 4) & 1) * 8;
        #pragma unroll
        for (int mi = 0; mi < 4; mi++) {
            const int scol = wm * 64 + mi * 16 + ((lane >> 3) & 1) * 8;
            ldsm4t(a[mi], sA + crow_l * 256 + ((((uint32_t)scol >> 3) * 16) ^ ((crow_l & 7) * 16)));
        }
        const int kc = ks * 2 + (lane >> 4);
        uint32_t b[4][2];
        #pragma unroll
        for (int nh = 0; nh < 2; nh++) {
            const int row = wn * 32 + nh * 16 + (lane & 15);
            uint32_t r4[4];
            ldsm4(r4, sB + row * 128 + (((uint32_t)kc * 16) ^ ((row & 7) * 16)));
            b[nh * 2 + 0][0] = r4[0]; b[nh * 2 + 0][1] = r4[2];
            b[nh * 2 + 1][0] = r4[1]; b[nh * 2 + 1][1] = r4[3];
        }
        #pragma unroll
        for (int mi = 0; mi < 4; mi++)
            #pragma unroll
            for (int ni = 0; ni < 4; ni++)
                mma16816(acc[mi][ni], a[mi], b[ni][0], b[ni][1]);
    }
}

#define ZERO_ACC4(acc) do { \
    _Pragma("unroll") for (int _a = 0; _a < 4; _a++) \
    _Pragma("unroll") for (int _b = 0; _b < 4; _b++) \
    _Pragma("unroll") for (int _c = 0; _c < 4; _c++) acc[_a][_b][_c] = 0.0f; } while (0)

// ============================ tiny prep: weights -> bf16, Z -> 0 ============================
__global__ __launch_bounds__(256) void prep_w(const float4* __restrict__ theta_w,
                                              const float4* __restrict__ phi_w,
                                              const float4* __restrict__ proj_w,
                                              uint2* __restrict__ w2,
                                              float* __restrict__ Z)
{
    const int gt = blockIdx.x * blockDim.x + threadIdx.x;   // 0..32767
    if (gt < NBATCH * SDIM) Z[gt] = 0.0f;
    if (gt < 8192) {        // theta_w, phi_w: 128x256 each = 8192 float4
        float4 v = theta_w[gt];
        __nv_bfloat162 a = __floats2bfloat162_rn(v.x, v.y);
        __nv_bfloat162 b = __floats2bfloat162_rn(v.z, v.w);
        w2[gt] = make_uint2(*reinterpret_cast<uint32_t*>(&a), *reinterpret_cast<uint32_t*>(&b));
        v = phi_w[gt];
        a = __floats2bfloat162_rn(v.x, v.y);
        b = __floats2bfloat162_rn(v.z, v.w);
        w2[8192 + gt] = make_uint2(*reinterpret_cast<uint32_t*>(&a), *reinterpret_cast<uint32_t*>(&b));
    }
    if (gt < 16384) {       // proj_w: 256x256 -> w2 rows 256-511
        float4 v = proj_w[gt];
        __nv_bfloat162 a = __floats2bfloat162_rn(v.x, v.y);
        __nv_bfloat162 b = __floats2bfloat162_rn(v.z, v.w);
        w2[16384 + gt] = make_uint2(*reinterpret_cast<uint32_t*>(&a), *reinterpret_cast<uint32_t*>(&b));
    }
}

// ============================ projections (HMMA trans-A, inline fp32->bf16 A conversion) ============================
// tp[s][o] = sum_c x[c,s] * w2[o,c].  A tiles read directly from fp32 x.
// grid (4 o-tiles, 32 s-tiles, 4), 256 thr, 96KB smem.
#define SA2(st) ((uint32_t)((st) * 32768))
#define SB2(st) ((uint32_t)((st) * 32768 + 16384))
__global__ __launch_bounds__(256)
void projections_hmma(const float* __restrict__ x,
                      const __nv_bfloat16* __restrict__ w2,
                      __nv_bfloat16* __restrict__ tp)
{
    extern __shared__ char smem[];
    const uint32_t sb = smem_u32(smem);
    const int tid = threadIdx.x, lane = tid & 31, wid = tid >> 5;
    const int wm = wid & 1, wn = wid >> 1;
    const int z = blockIdx.z, m0 = blockIdx.y * 128, n0 = blockIdx.x * 128;

    const float* Abase = x + (size_t)z * CDIM * SDIM + m0;   // rows c (K), cols s; ld SDIM
    const __nv_bfloat16* Bbase = w2 + (size_t)n0 * 256;

    // per-thread A-chunk coords (4 chunks of 8 elems in a 64x128 tile)
    int rr[4], kk[4];
    #pragma unroll
    for (int i = 0; i < 4; i++) {
        const int c = tid + i * 256;
        rr[i] = c >> 4;        // row in 0..63 (channel within k-chunk)
        kk[i] = (c & 15) * 8;  // col offset 0..120
    }

    float acc[4][4][4];
    ZERO_ACC4(acc);

    // prologue: prefetch A chunk kt=0 into regs; cp.async B0
    uint32_t pre[4][4];
    #pragma unroll
    for (int i = 0; i < 4; i++)
        ldg_cvt8(Abase + (size_t)rr[i] * SDIM + kk[i], pre[i]);
    load_tileT<128, 256>(sb + SB2(0), Bbase, 256);
    CP_COMMIT();

    const int KT = 4;
    #pragma unroll
    for (int kt = 0; kt < KT; kt++) {
        // store prefetched A regs into buffer kt&1 (swizzled)
        #pragma unroll
        for (int i = 0; i < 4; i++) {
            const uint32_t so = sb + SA2(kt & 1) + rr[i] * 256
                              + (((uint32_t)(kk[i] * 2)) ^ ((rr[i] & 7) * 16));
            sts128(so, pre[i]);
        }
        // prefetch next A chunk (overlaps sync + compute)
        if (kt + 1 < KT) {
            const float* An = Abase + (size_t)(kt + 1) * 64 * SDIM;
            #pragma unroll
            for (int i = 0; i < 4; i++)
                ldg_cvt8(An + (size_t)rr[i] * SDIM + kk[i], pre[i]);
            load_tileT<128, 256>(sb + SB2((kt + 1) & 1), Bbase + (kt + 1) * 64, 256);
            CP_COMMIT();
            CP_WAIT(1);
        } else {
            CP_WAIT(0);
        }
        __syncthreads();
        compute_chunk_At(sb + SA2(kt & 1), sb + SB2(kt & 1), wm, wn, lane, acc);
        __syncthreads();
    }

    const int lrow = lane >> 2, lcol2 = (lane & 3) * 2;
    #pragma unroll
    for (int mi = 0; mi < 4; mi++) {
        const int gr0 = m0 + wm * 64 + mi * 16 + lrow;   // s
        #pragma unroll
        for (int ni = 0; ni < 4; ni++) {
            const int col = n0 + wn * 32 + ni * 8 + lcol2;  // o in [0,512)
            __nv_bfloat162 h0 = __floats2bfloat162_rn(acc[mi][ni][0], acc[mi][ni][1]);
            __nv_bfloat162 h1 = __floats2bfloat162_rn(acc[mi][ni][2], acc[mi][ni][3]);
            *reinterpret_cast<uint32_t*>(tp + ((size_t)z * SDIM + gr0) * 512 + col) =
                *reinterpret_cast<uint32_t*>(&h0);
            *reinterpret_cast<uint32_t*>(tp + ((size_t)z * SDIM + gr0 + 8) * 512 + col) =
                *reinterpret_cast<uint32_t*>(&h1);
        }
    }
}

// ============================ fused logits + exp (R4-proven shape, ld=512) ============================
__global__ __launch_bounds__(256)
void logits_exp_hmma(const __nv_bfloat16* __restrict__ tp,
                     __nv_bfloat16* __restrict__ f,
                     float* __restrict__ Z)
{
    extern __shared__ char smem[];
    const uint32_t sb = smem_u32(smem);
    const int tid = threadIdx.x, lane = tid & 31, wid = tid >> 5;
    const int wm = wid & 1, wn = wid >> 1;
    const int z = blockIdx.z, m0 = blockIdx.y * 128, n0 = blockIdx.x * 128;

    const __nv_bfloat16* Abase = tp + ((size_t)(z * SDIM + m0)) * 512;        // theta
    const __nv_bfloat16* Bbase = tp + ((size_t)(z * SDIM + n0)) * 512 + 128;  // phi

    float acc[4][4][4];
    ZERO_ACC4(acc);

    load_tileT<128, 256>(sb + SA2(0), Abase, 512);
    load_tileT<128, 256>(sb + SB2(0), Bbase, 512);
    CP_COMMIT();
    load_tileT<128, 256>(sb + SA2(1), Abase + 64, 512);
    load_tileT<128, 256>(sb + SB2(1), Bbase + 64, 512);
    CP_COMMIT();

    CP_WAIT(1);
    __syncthreads();
    compute_chunk(sb + SA2(0), sb + SB2(0), wm * 64, wn * 32, lane, acc);
    CP_WAIT(0);
    __syncthreads();
    compute_chunk(sb + SA2(1), sb + SB2(1), wm * 64, wn * 32, lane, acc);

    const float alpha = 0.08838834764831845f; // 1/sqrt(128)
    const int lrow = lane >> 2, lcol2 = (lane & 3) * 2;
    #pragma unroll
    for (int mi = 0; mi < 4; mi++) {
        const int gr0 = m0 + wm * 64 + mi * 16 + lrow;
        const int gr1 = gr0 + 8;
        float rs0 = 0.0f, rs1 = 0.0f;
        #pragma unroll
        for (int ni = 0; ni < 4; ni++) {
            const int col = n0 + wn * 32 + ni * 8 + lcol2;
            float e00 = __expf(acc[mi][ni][0] * alpha);
            float e01 = __expf(acc[mi][ni][1] * alpha);
            float e10 = __expf(acc[mi][ni][2] * alpha);
            float e11 = __expf(acc[mi][ni][3] * alpha);
            rs0 += e00 + e01; rs1 += e10 + e11;
            __nv_bfloat162 h0 = __floats2bfloat162_rn(e00, e01);
            __nv_bfloat162 h1 = __floats2bfloat162_rn(e10, e11);
            *reinterpret_cast<uint32_t*>(f + ((size_t)z * SDIM + gr0) * SDIM + col) =
                *reinterpret_cast<uint32_t*>(&h0);
            *reinterpret_cast<uint32_t*>(f + ((size_t)z * SDIM + gr1) * SDIM + col) =
                *reinterpret_cast<uint32_t*>(&h1);
        }
        rs0 += __shfl_xor_sync(0xffffffffu, rs0, 1);
        rs0 += __shfl_xor_sync(0xffffffffu, rs0, 2);
        rs1 += __shfl_xor_sync(0xffffffffu, rs1, 1);
        rs1 += __shfl_xor_sync(0xffffffffu, rs1, 2);
        if ((lane & 3) == 0) {
            atomicAdd(&Z[(size_t)z * SDIM + gr0], rs0);
            atomicAdd(&Z[(size_t)z * SDIM + gr1], rs1);
        }
    }
}

// ============================ fused attend+proj (trans-A HMMA, 3-stage) ============================
// out[n][o][s] = x[n][o][s] + (1/Z[s]) * sum_t xp[o,t] * f[s,t]
#define ASA(st) ((uint32_t)((st) * 32768))
#define ASB(st) ((uint32_t)((st) * 32768 + 16384))
__global__ __launch_bounds__(256)
void attend_proj_hmma(const __nv_bfloat16* __restrict__ tp,
                      const __nv_bfloat16* __restrict__ f,
                      const float* __restrict__ Z,
                      const float* __restrict__ x,
                      float* __restrict__ out)
{
    extern __shared__ char smem[];
    const uint32_t sb = smem_u32(smem);
    const int tid = threadIdx.x, lane = tid & 31, wid = tid >> 5;
    const int wm = wid & 1, wn = wid >> 1;
    const int z = blockIdx.z, m0 = blockIdx.y * 128, n0 = blockIdx.x * 128;

    const __nv_bfloat16* Abase = tp + (size_t)z * SDIM * 512 + 256 + m0;   // rows t, ld 512
    const __nv_bfloat16* Bbase = f + ((size_t)z * SDIM + n0) * SDIM;       // rows s, ld SDIM

    float acc[4][4][4];
    ZERO_ACC4(acc);

    load_tile_64x128(sb + ASA(0), Abase, 512);
    load_tileT<128, 256>(sb + ASB(0), Bbase, SDIM);
    CP_COMMIT();
    load_tile_64x128(sb + ASA(1), Abase + (size_t)64 * 512, 512);
    load_tileT<128, 256>(sb + ASB(1), Bbase + 64, SDIM);
    CP_COMMIT();

    const int KT = SDIM / 64; // 64
    for (int kt = 0; kt < KT; kt++) {
        if (kt + 1 < KT) { CP_WAIT(1); } else { CP_WAIT(0); }
        __syncthreads();
        if (kt + 2 < KT) {
            const int st = (kt + 2) % 3;
            load_tile_64x128(sb + ASA(st), Abase + (size_t)(kt + 2) * 64 * 512, 512);
            load_tileT<128, 256>(sb + ASB(st), Bbase + (kt + 2) * 64, SDIM);
            CP_COMMIT();
        }
        compute_chunk_At(sb + ASA(kt % 3), sb + ASB(kt % 3), wm, wn, lane, acc);
    }

    // epilogue: rows = o, cols = s; scale by 1/Z[s], add residual x, fp32 out
    const int lrow = lane >> 2, lcol2 = (lane & 3) * 2;
    #pragma unroll
    for (int ni = 0; ni < 4; ni++) {
        const int col = n0 + wn * 32 + ni * 8 + lcol2;   // s (even)
        const float2 zc = *reinterpret_cast<const float2*>(&Z[(size_t)z * SDIM + col]);
        const float izx = 1.0f / zc.x, izy = 1.0f / zc.y;
        #pragma unroll
        for (int mi = 0; mi < 4; mi++) {
            const int gr0 = m0 + wm * 64 + mi * 16 + lrow;   // o
            const int gr1 = gr0 + 8;
            const float2 x0 = *reinterpret_cast<const float2*>(x + ((size_t)z * CDIM + gr0) * SDIM + col);
            const float2 x1 = *reinterpret_cast<const float2*>(x + ((size_t)z * CDIM + gr1) * SDIM + col);
            float2 v0 = make_float2(acc[mi][ni][0] * izx + x0.x, acc[mi][ni][1] * izy + x0.y);
            float2 v1 = make_float2(acc[mi][ni][2] * izx + x1.x, acc[mi][ni][3] * izy + x1.y);
            *reinterpret_cast<float2*>(out + ((size_t)z * CDIM + gr0) * SDIM + col) = v0;
            *reinterpret_cast<float2*>(out + ((size_t)z * CDIM + gr1) * SDIM + col) = v1;
        }
    }
}

// ============================ launch ============================
extern "C" void kernel_launch(void* const* d_in, const int* in_sizes, int n_in,
                              void* d_out, int out_size)
{
    const float* x       = (const float*)d_in[0];
    const float* theta_w = (const float*)d_in[1];
    const float* phi_w   = (const float*)d_in[2];
    const float* proj_w  = (const float*)d_in[3];
    float* out = (float*)d_out;

    __nv_bfloat16 *tp, *f, *w2;
    float *Z;
    cudaGetSymbolAddress((void**)&tp, g_tp);
    cudaGetSymbolAddress((void**)&f,  g_f);
    cudaGetSymbolAddress((void**)&w2, g_w2);
    cudaGetSymbolAddress((void**)&Z,  g_Z);

    cudaFuncSetAttribute(projections_hmma, cudaFuncAttributeMaxDynamicSharedMemorySize, 98304);
    cudaFuncSetAttribute(logits_exp_hmma,  cudaFuncAttributeMaxDynamicSharedMemorySize, 65536);
    cudaFuncSetAttribute(attend_proj_hmma, cudaFuncAttributeMaxDynamicSharedMemorySize, 98304);

    // 0: weights -> bf16, Z -> 0 (tiny)
    prep_w<<<128, 256>>>((const float4*)theta_w, (const float4*)phi_w,
                         (const float4*)proj_w, (uint2*)w2, Z);

    // 1: all three projections (theta, phi, xp = proj_w @ x), inline fp32->bf16 A
    projections_hmma<<<dim3(4, 32, 4), 256, 98304>>>(x, w2, tp);

    // 2: fused logits -> exp + row sums
    logits_exp_hmma<<<dim3(32, 32, 4), 256, 65536>>>(tp, f, Z);

    // 3: fused attend + projection + residual + 1/Z
    attend_proj_hmma<<<dim3(32, 2, 4), 256, 98304>>>(tp, f, Z, x, out);
}

// round 11
// speedup vs baseline: 1.0115x; 1.0115x over previous
#include <cuda_runtime.h>
#include <cuda_bf16.h>
#include <math.h>
#include <cstdint>

#define SDIM 4096
#define CDIM 256
#define EDIM 128
#define NBATCH 4

// ---- scratch (device globals: allocation-free) ----
// tp rows = spatial s/t, 512 cols: [0:128)=theta, [128:256)=phi, [256:512)=xp^T (= (proj_w@x)[o,t])
__device__ __nv_bfloat16 g_tp[(size_t)NBATCH * SDIM * 512];
__device__ __nv_bfloat16 g_f [(size_t)NBATCH * SDIM * SDIM];       // unnormalized exp(logits)
__device__ __nv_bfloat16 g_xb[(size_t)NBATCH * CDIM * SDIM];       // x bf16 [n][c][s]
__device__ __nv_bfloat16 g_w2[512 * 256];                          // rows: 0-127 theta_w, 128-255 phi_w, 256-511 proj_w
__device__ float         g_Z [(size_t)NBATCH * SDIM];              // row sums

// ============================ low-level helpers ============================
__device__ __forceinline__ uint32_t smem_u32(const void* p) {
    uint32_t a;
    asm("{ .reg .u64 t; cvta.to.shared.u64 t, %1; cvt.u32.u64 %0, t; }" : "=r"(a) : "l"(p));
    return a;
}
__device__ __forceinline__ void ldsm4(uint32_t r[4], uint32_t addr) {
    asm volatile("ldmatrix.sync.aligned.m8n8.x4.shared.b16 {%0,%1,%2,%3}, [%4];"
                 : "=r"(r[0]), "=r"(r[1]), "=r"(r[2]), "=r"(r[3]) : "r"(addr));
}
__device__ __forceinline__ void ldsm4t(uint32_t r[4], uint32_t addr) {
    asm volatile("ldmatrix.sync.aligned.m8n8.x4.trans.shared.b16 {%0,%1,%2,%3}, [%4];"
                 : "=r"(r[0]), "=r"(r[1]), "=r"(r[2]), "=r"(r[3]) : "r"(addr));
}
__device__ __forceinline__ void mma16816(float c[4], const uint32_t a[4], uint32_t b0, uint32_t b1) {
    asm volatile("mma.sync.aligned.m16n8k16.row.col.f32.bf16.bf16.f32 "
                 "{%0,%1,%2,%3},{%4,%5,%6,%7},{%8,%9},{%0,%1,%2,%3};"
                 : "+f"(c[0]), "+f"(c[1]), "+f"(c[2]), "+f"(c[3])
                 : "r"(a[0]), "r"(a[1]), "r"(a[2]), "r"(a[3]), "r"(b0), "r"(b1));
}
__device__ __forceinline__ void cp16(uint32_t saddr, const void* g) {
    asm volatile("cp.async.cg.shared.global [%0], [%1], 16;" :: "r"(saddr), "l"(g));
}
#define CP_COMMIT() asm volatile("cp.async.commit_group;" ::: "memory")
#define CP_WAIT(N)  asm volatile("cp.async.wait_group %0;" :: "n"(N) : "memory")

// R rows x 64 cols bf16 (128B rows), XOR-16B swizzle keyed on row&7. NT threads.
template<int R, int NT>
__device__ __forceinline__ void load_tileT(uint32_t sdst, const __nv_bfloat16* g, int ldg) {
    const int tid = threadIdx.x;
    #pragma unroll
    for (int i = 0; i < (R * 8) / NT; i++) {
        const int c = tid + i * NT;
        const int r = c >> 3, kc = c & 7;
        const uint32_t so = sdst + r * 128 + (((uint32_t)kc * 16) ^ ((r & 7) * 16));
        cp16(so, g + (size_t)r * ldg + kc * 8);
    }
}
// 64 rows x 128 cols bf16 (256B rows), 256 threads (trans-A operand tile).
__device__ __forceinline__ void load_tile_64x128(uint32_t sdst, const __nv_bfloat16* g, int ldg) {
    const int tid = threadIdx.x;
    #pragma unroll
    for (int i = 0; i < 4; i++) {
        const int c = tid + i * 256;
        const int r = c >> 4, kc = c & 15;
        const uint32_t so = sdst + r * 256 + (((uint32_t)kc * 16) ^ ((r & 7) * 16));
        cp16(so, g + (size_t)r * ldg + kc * 8);
    }
}

// ---- 64x32 warp-tile chunk (regular A) ----
__device__ __forceinline__ void compute_chunk(uint32_t sA, uint32_t sB,
                                              int m_base, int n_base, int lane,
                                              float acc[4][4][4]) {
    #pragma unroll
    for (int ks = 0; ks < 4; ks++) {
        const int kc = ks * 2 + (lane >> 4);
        uint32_t a[4][4];
        #pragma unroll
        for (int mi = 0; mi < 4; mi++) {
            const int row = m_base + mi * 16 + (lane & 15);
            ldsm4(a[mi], sA + row * 128 + (((uint32_t)kc * 16) ^ ((row & 7) * 16)));
        }
        uint32_t b[4][2];
        #pragma unroll
        for (int nh = 0; nh < 2; nh++) {
            const int row = n_base + nh * 16 + (lane & 15);
            uint32_t r4[4];
            ldsm4(r4, sB + row * 128 + (((uint32_t)kc * 16) ^ ((row & 7) * 16)));
            b[nh * 2 + 0][0] = r4[0]; b[nh * 2 + 0][1] = r4[2];
            b[nh * 2 + 1][0] = r4[1]; b[nh * 2 + 1][1] = r4[3];
        }
        #pragma unroll
        for (int mi = 0; mi < 4; mi++)
            #pragma unroll
            for (int ni = 0; ni < 4; ni++)
                mma16816(acc[mi][ni], a[mi], b[ni][0], b[ni][1]);
    }
}

// ---- trans-A chunk: A stored [k][m] (64 rows x 128 cols, 256B rows), B regular [n][k] ----
__device__ __forceinline__ void compute_chunk_At(uint32_t sA, uint32_t sB,
                                                 int wm, int wn, int lane,
                                                 float acc[4][4][4]) {
    #pragma unroll
    for (int ks = 0; ks < 4; ks++) {
        uint32_t a[4][4];
        const int crow_l = ks * 16 + (lane & 7) + ((lane >> 4) & 1) * 8;
        #pragma unroll
        for (int mi = 0; mi < 4; mi++) {
            const int scol = wm * 64 + mi * 16 + ((lane >> 3) & 1) * 8;
            ldsm4t(a[mi], sA + crow_l * 256 + ((((uint32_t)scol >> 3) * 16) ^ ((crow_l & 7) * 16)));
        }
        const int kc = ks * 2 + (lane >> 4);
        uint32_t b[4][2];
        #pragma unroll
        for (int nh = 0; nh < 2; nh++) {
            const int row = wn * 32 + nh * 16 + (lane & 15);
            uint32_t r4[4];
            ldsm4(r4, sB + row * 128 + (((uint32_t)kc * 16) ^ ((row & 7) * 16)));
            b[nh * 2 + 0][0] = r4[0]; b[nh * 2 + 0][1] = r4[2];
            b[nh * 2 + 1][0] = r4[1]; b[nh * 2 + 1][1] = r4[3];
        }
        #pragma unroll
        for (int mi = 0; mi < 4; mi++)
            #pragma unroll
            for (int ni = 0; ni < 4; ni++)
                mma16816(acc[mi][ni], a[mi], b[ni][0], b[ni][1]);
    }
}

#define ZERO_ACC4(acc) do { \
    _Pragma("unroll") for (int _a = 0; _a < 4; _a++) \
    _Pragma("unroll") for (int _b = 0; _b < 4; _b++) \
    _Pragma("unroll") for (int _c = 0; _c < 4; _c++) acc[_a][_b][_c] = 0.0f; } while (0)

// ============================ prep (R9-proven): x -> bf16, weights -> bf16, Z -> 0 ============================
__global__ __launch_bounds__(256) void prep_bf16(const float4* __restrict__ x,
                                                 const float4* __restrict__ theta_w,
                                                 const float4* __restrict__ phi_w,
                                                 const float4* __restrict__ proj_w,
                                                 uint2* __restrict__ xb,
                                                 uint2* __restrict__ w2,
                                                 float* __restrict__ Z, int n4)
{
    const int gt = blockIdx.x * blockDim.x + threadIdx.x;
    const int stride = gridDim.x * blockDim.x;
    if (gt < NBATCH * SDIM) Z[gt] = 0.0f;
    for (int i = gt; i < n4; i += stride) {
        float4 v = x[i];
        __nv_bfloat162 a = __floats2bfloat162_rn(v.x, v.y);
        __nv_bfloat162 b = __floats2bfloat162_rn(v.z, v.w);
        xb[i] = make_uint2(*reinterpret_cast<uint32_t*>(&a), *reinterpret_cast<uint32_t*>(&b));
    }
    if (gt < 8192) {        // theta_w, phi_w: 128x256 each
        float4 v = theta_w[gt];
        __nv_bfloat162 a = __floats2bfloat162_rn(v.x, v.y);
        __nv_bfloat162 b = __floats2bfloat162_rn(v.z, v.w);
        w2[gt] = make_uint2(*reinterpret_cast<uint32_t*>(&a), *reinterpret_cast<uint32_t*>(&b));
        v = phi_w[gt];
        a = __floats2bfloat162_rn(v.x, v.y);
        b = __floats2bfloat162_rn(v.z, v.w);
        w2[8192 + gt] = make_uint2(*reinterpret_cast<uint32_t*>(&a), *reinterpret_cast<uint32_t*>(&b));
    }
    if (gt < 16384) {       // proj_w: 256x256 -> w2 rows 256-511
        float4 v = proj_w[gt];
        __nv_bfloat162 a = __floats2bfloat162_rn(v.x, v.y);
        __nv_bfloat162 b = __floats2bfloat162_rn(v.z, v.w);
        w2[16384 + gt] = make_uint2(*reinterpret_cast<uint32_t*>(&a), *reinterpret_cast<uint32_t*>(&b));
    }
}

// ============================ projections (R9-proven, HMMA trans-A) ============================
// tp[s][o] = sum_c xb[c,s] * w2[o,c]. theta (o 0-127), phi (128-255), xp^T (256-511).
#define SA2(st) ((uint32_t)((st) * 32768))
#define SB2(st) ((uint32_t)((st) * 32768 + 16384))
__global__ __launch_bounds__(256)
void projections_hmma(const __nv_bfloat16* __restrict__ xb,
                      const __nv_bfloat16* __restrict__ w2,
                      __nv_bfloat16* __restrict__ tp)
{
    extern __shared__ char smem[];
    const uint32_t sb = smem_u32(smem);
    const int tid = threadIdx.x, lane = tid & 31, wid = tid >> 5;
    const int wm = wid & 1, wn = wid >> 1;
    const int z = blockIdx.z, m0 = blockIdx.y * 128, n0 = blockIdx.x * 128;

    const __nv_bfloat16* Abase = xb + (size_t)z * CDIM * SDIM + m0;
    const __nv_bfloat16* Bbase = w2 + (size_t)n0 * 256;

    float acc[4][4][4];
    ZERO_ACC4(acc);

    load_tile_64x128(sb + SA2(0), Abase, SDIM);
    load_tileT<128, 256>(sb + SB2(0), Bbase, 256);
    CP_COMMIT();

    const int KT = 4;
    #pragma unroll
    for (int kt = 0; kt < KT; kt++) {
        if (kt + 1 < KT) {
            load_tile_64x128(sb + SA2((kt + 1) & 1), Abase + (size_t)(kt + 1) * 64 * SDIM, SDIM);
            load_tileT<128, 256>(sb + SB2((kt + 1) & 1), Bbase + (kt + 1) * 64, 256);
            CP_COMMIT();
            CP_WAIT(1);
        } else {
            CP_WAIT(0);
        }
        __syncthreads();
        compute_chunk_At(sb + SA2(kt & 1), sb + SB2(kt & 1), wm, wn, lane, acc);
        __syncthreads();
    }

    const int lrow = lane >> 2, lcol2 = (lane & 3) * 2;
    #pragma unroll
    for (int mi = 0; mi < 4; mi++) {
        const int gr0 = m0 + wm * 64 + mi * 16 + lrow;   // s
        #pragma unroll
        for (int ni = 0; ni < 4; ni++) {
            const int col = n0 + wn * 32 + ni * 8 + lcol2;  // o in [0,512)
            __nv_bfloat162 h0 = __floats2bfloat162_rn(acc[mi][ni][0], acc[mi][ni][1]);
            __nv_bfloat162 h1 = __floats2bfloat162_rn(acc[mi][ni][2], acc[mi][ni][3]);
            *reinterpret_cast<uint32_t*>(tp + ((size_t)z * SDIM + gr0) * 512 + col) =
                *reinterpret_cast<uint32_t*>(&h0);
            *reinterpret_cast<uint32_t*>(tp + ((size_t)z * SDIM + gr0 + 8) * 512 + col) =
                *reinterpret_cast<uint32_t*>(&h1);
        }
    }
}

// ============================ fused logits + exp (theta-resident, 4 phi tiles, 96KB, 2 CTAs/SM) ============================
// smem: theta A chunk0 @0, chunk1 @16K (32KB resident); phi buf in {0,1}: chunk0 @32K+buf*32K, chunk1 @+16K.
#define LTA(ch)      ((uint32_t)((ch) * 16384))
#define LPB(buf, ch) ((uint32_t)(32768 + (buf) * 32768 + (ch) * 16384))
__global__ __launch_bounds__(256, 2)
void logits_exp_hmma(const __nv_bfloat16* __restrict__ tp,
                     __nv_bfloat16* __restrict__ f,
                     float* __restrict__ Z)
{
    extern __shared__ char smem[];
    const uint32_t sb = smem_u32(smem);
    const int tid = threadIdx.x, lane = tid & 31, wid = tid >> 5;
    const int wm = wid & 1, wn = wid >> 1;
    const int z = blockIdx.z, m0 = blockIdx.y * 128, n0 = blockIdx.x * 512;

    const __nv_bfloat16* Abase = tp + ((size_t)(z * SDIM + m0)) * 512;        // theta
    const __nv_bfloat16* Bbase = tp + ((size_t)(z * SDIM + n0)) * 512 + 128;  // phi: 4 tiles of 128 rows

    const float alpha = 0.08838834764831845f; // 1/sqrt(128)
    const int lrow = lane >> 2, lcol2 = (lane & 3) * 2;

    // prologue: theta (both K chunks) + phi tile 0 -> group 0; phi tile 1 -> group 1
    load_tileT<128, 256>(sb + LTA(0), Abase, 512);
    load_tileT<128, 256>(sb + LTA(1), Abase + 64, 512);
    load_tileT<128, 256>(sb + LPB(0, 0), Bbase, 512);
    load_tileT<128, 256>(sb + LPB(0, 1), Bbase + 64, 512);
    CP_COMMIT();
    load_tileT<128, 256>(sb + LPB(1, 0), Bbase + (size_t)128 * 512, 512);
    load_tileT<128, 256>(sb + LPB(1, 1), Bbase + (size_t)128 * 512 + 64, 512);
    CP_COMMIT();

    for (int p = 0; p < 4; p++) {
        if (p < 3) { CP_WAIT(1); } else { CP_WAIT(0); }   // phi tile p resident
        __syncthreads();

        float acc[4][4][4];
        ZERO_ACC4(acc);
        const int buf = p & 1;
        compute_chunk(sb + LTA(0), sb + LPB(buf, 0), wm * 64, wn * 32, lane, acc);
        compute_chunk(sb + LTA(1), sb + LPB(buf, 1), wm * 64, wn * 32, lane, acc);

        __syncthreads();   // all warps done reading phi buf before it is overwritten
        if (p + 2 < 4) {   // prefetch phi tile p+2 into buf (overlaps epilogue + next compute)
            const __nv_bfloat16* pb = Bbase + (size_t)(p + 2) * 128 * 512;
            load_tileT<128, 256>(sb + LPB(buf, 0), pb, 512);
            load_tileT<128, 256>(sb + LPB(buf, 1), pb + 64, 512);
            CP_COMMIT();
        }

        // epilogue for this 128x128 tile
        #pragma unroll
        for (int mi = 0; mi < 4; mi++) {
            const int gr0 = m0 + wm * 64 + mi * 16 + lrow;
            const int gr1 = gr0 + 8;
            float rs0 = 0.0f, rs1 = 0.0f;
            #pragma unroll
            for (int ni = 0; ni < 4; ni++) {
                const int col = n0 + p * 128 + wn * 32 + ni * 8 + lcol2;
                float e00 = __expf(acc[mi][ni][0] * alpha);
                float e01 = __expf(acc[mi][ni][1] * alpha);
                float e10 = __expf(acc[mi][ni][2] * alpha);
                float e11 = __expf(acc[mi][ni][3] * alpha);
                rs0 += e00 + e01; rs1 += e10 + e11;
                __nv_bfloat162 h0 = __floats2bfloat162_rn(e00, e01);
                __nv_bfloat162 h1 = __floats2bfloat162_rn(e10, e11);
                *reinterpret_cast<uint32_t*>(f + ((size_t)z * SDIM + gr0) * SDIM + col) =
                    *reinterpret_cast<uint32_t*>(&h0);
                *reinterpret_cast<uint32_t*>(f + ((size_t)z * SDIM + gr1) * SDIM + col) =
                    *reinterpret_cast<uint32_t*>(&h1);
            }
            rs0 += __shfl_xor_sync(0xffffffffu, rs0, 1);
            rs0 += __shfl_xor_sync(0xffffffffu, rs0, 2);
            rs1 += __shfl_xor_sync(0xffffffffu, rs1, 1);
            rs1 += __shfl_xor_sync(0xffffffffu, rs1, 2);
            if ((lane & 3) == 0) {
                atomicAdd(&Z[(size_t)z * SDIM + gr0], rs0);
                atomicAdd(&Z[(size_t)z * SDIM + gr1], rs1);
            }
        }
    }
}

// ============================ fused attend+proj (R9-proven, trans-A HMMA, 3-stage) ============================
// out[n][o][s] = x[n][o][s] + (1/Z[s]) * sum_t xp[o,t] * f[s,t]
#define ASA(st) ((uint32_t)((st) * 32768))
#define ASB(st) ((uint32_t)((st) * 32768 + 16384))
__global__ __launch_bounds__(256)
void attend_proj_hmma(const __nv_bfloat16* __restrict__ tp,
                      const __nv_bfloat16* __restrict__ f,
                      const float* __restrict__ Z,
                      const float* __restrict__ x,
                      float* __restrict__ out)
{
    extern __shared__ char smem[];
    const uint32_t sb = smem_u32(smem);
    const int tid = threadIdx.x, lane = tid & 31, wid = tid >> 5;
    const int wm = wid & 1, wn = wid >> 1;
    const int z = blockIdx.z, m0 = blockIdx.y * 128, n0 = blockIdx.x * 128;

    const __nv_bfloat16* Abase = tp + (size_t)z * SDIM * 512 + 256 + m0;   // rows t, ld 512
    const __nv_bfloat16* Bbase = f + ((size_t)z * SDIM + n0) * SDIM;       // rows s, ld SDIM

    float acc[4][4][4];
    ZERO_ACC4(acc);

    load_tile_64x128(sb + ASA(0), Abase, 512);
    load_tileT<128, 256>(sb + ASB(0), Bbase, SDIM);
    CP_COMMIT();
    load_tile_64x128(sb + ASA(1), Abase + (size_t)64 * 512, 512);
    load_tileT<128, 256>(sb + ASB(1), Bbase + 64, SDIM);
    CP_COMMIT();

    const int KT = SDIM / 64; // 64
    for (int kt = 0; kt < KT; kt++) {
        if (kt + 1 < KT) { CP_WAIT(1); } else { CP_WAIT(0); }
        __syncthreads();
        if (kt + 2 < KT) {
            const int st = (kt + 2) % 3;
            load_tile_64x128(sb + ASA(st), Abase + (size_t)(kt + 2) * 64 * 512, 512);
            load_tileT<128, 256>(sb + ASB(st), Bbase + (kt + 2) * 64, SDIM);
            CP_COMMIT();
        }
        compute_chunk_At(sb + ASA(kt % 3), sb + ASB(kt % 3), wm, wn, lane, acc);
    }

    // epilogue: rows = o, cols = s; scale by 1/Z[s], add residual x, fp32 out
    const int lrow = lane >> 2, lcol2 = (lane & 3) * 2;
    #pragma unroll
    for (int ni = 0; ni < 4; ni++) {
        const int col = n0 + wn * 32 + ni * 8 + lcol2;   // s (even)
        const float2 zc = *reinterpret_cast<const float2*>(&Z[(size_t)z * SDIM + col]);
        const float izx = 1.0f / zc.x, izy = 1.0f / zc.y;
        #pragma unroll
        for (int mi = 0; mi < 4; mi++) {
            const int gr0 = m0 + wm * 64 + mi * 16 + lrow;   // o
            const int gr1 = gr0 + 8;
            const float2 x0 = *reinterpret_cast<const float2*>(x + ((size_t)z * CDIM + gr0) * SDIM + col);
            const float2 x1 = *reinterpret_cast<const float2*>(x + ((size_t)z * CDIM + gr1) * SDIM + col);
            float2 v0 = make_float2(acc[mi][ni][0] * izx + x0.x, acc[mi][ni][1] * izy + x0.y);
            float2 v1 = make_float2(acc[mi][ni][2] * izx + x1.x, acc[mi][ni][3] * izy + x1.y);
            *reinterpret_cast<float2*>(out + ((size_t)z * CDIM + gr0) * SDIM + col) = v0;
            *reinterpret_cast<float2*>(out + ((size_t)z * CDIM + gr1) * SDIM + col) = v1;
        }
    }
}

// ============================ launch ============================
extern "C" void kernel_launch(void* const* d_in, const int* in_sizes, int n_in,
                              void* d_out, int out_size)
{
    const float* x       = (const float*)d_in[0];
    const float* theta_w = (const float*)d_in[1];
    const float* phi_w   = (const float*)d_in[2];
    const float* proj_w  = (const float*)d_in[3];
    float* out = (float*)d_out;

    __nv_bfloat16 *tp, *f, *xb, *w2;
    float *Z;
    cudaGetSymbolAddress((void**)&tp, g_tp);
    cudaGetSymbolAddress((void**)&f,  g_f);
    cudaGetSymbolAddress((void**)&xb, g_xb);
    cudaGetSymbolAddress((void**)&w2, g_w2);
    cudaGetSymbolAddress((void**)&Z,  g_Z);

    cudaFuncSetAttribute(projections_hmma, cudaFuncAttributeMaxDynamicSharedMemorySize, 65536);
    cudaFuncSetAttribute(logits_exp_hmma,  cudaFuncAttributeMaxDynamicSharedMemorySize, 98304);
    cudaFuncSetAttribute(attend_proj_hmma, cudaFuncAttributeMaxDynamicSharedMemorySize, 98304);

    // 0: bf16 conversions + Z zero (R9-proven)
    prep_bf16<<<1024, 256>>>((const float4*)x, (const float4*)theta_w, (const float4*)phi_w,
                             (const float4*)proj_w, (uint2*)xb, (uint2*)w2, Z,
                             (int)((size_t)NBATCH * CDIM * SDIM / 4));

    // 1: all three projections (theta, phi, xp = proj_w @ x) in one GEMM (R9-proven)
    projections_hmma<<<dim3(4, 32, 4), 256, 65536>>>(xb, w2, tp);

    // 2: fused logits -> exp + row sums (theta-resident, 96KB, 2 CTAs/SM)
    logits_exp_hmma<<<dim3(8, 32, 4), 256, 98304>>>(tp, f, Z);

    // 3: fused attend + projection + residual + 1/Z (R9-proven)
    attend_proj_hmma<<<dim3(32, 2, 4), 256, 98304>>>(tp, f, Z, x, out);
}